// round 17
// baseline (speedup 1.0000x reference)
#include <cuda_runtime.h>
#include <math_constants.h>
#include <cstdint>

// Problem constants
#define BB 4096
#define DD 1024
#define KK 32
#define MIN_BW 0.001f
#define MIN_BH 0.001f

#define FPB 32                 // features per block
#define RPB 64                 // rows per block
#define NSTRIP 2               // strips of 32 rows
#define FG  (DD / FPB)         // 32 feature groups
#define RG  (BB / RPB)         // 64 row groups
#define FPW (FPB / 8)          // 4 features per warp
#define XPITCH 65              // smem x-tile pitch (rows + 1)

// Precomputed per-feature spline data (device globals: allocation-free scratch)
__device__ float4 g_coef[DD * KK];      // {a, b, c, d} per (feature, bin)
__device__ float  g_cwl[DD * KK];       // left cumwidth per (feature, bin)
__device__ float  g_partial[BB * FG];   // per-(row, fgroup) log2 partial sums
__device__ int    g_cnt[RG];            // completion counters (self-resetting)

// ---------------------------------------------------------------------------
// Kernel 1: per-feature coefficient precompute. One warp per feature.
// ---------------------------------------------------------------------------
__global__ void __launch_bounds__(128) precompute_kernel(
    const float* __restrict__ uw, const float* __restrict__ uh,
    const float* __restrict__ udl, const float* __restrict__ udr)
{
    const unsigned FULL = 0xffffffffu;
    int warpId = threadIdx.x >> 5;
    int lane   = threadIdx.x & 31;
    int f = blockIdx.x * 4 + warpId;
    if (f >= DD) return;

    float w_in = __ldg(&uw[f * KK + lane]);
    float h_in = __ldg(&uh[f * KK + lane]);

    // softmax without max-subtraction (inputs ~N(0,1): exp safe in fp32)
    float ew = __expf(w_in);
    float eh = __expf(h_in);
    float sw = ew, sh = eh;
    #pragma unroll
    for (int o = 16; o; o >>= 1) {
        sw += __shfl_xor_sync(FULL, sw, o);
        sh += __shfl_xor_sync(FULL, sh, o);
    }
    float width  = MIN_BW + (1.0f - MIN_BW * (float)KK) * (ew / sw);
    float height = MIN_BH + (1.0f - MIN_BH * (float)KK) * (eh / sh);

    // inclusive cumsums (interleaved chains)
    float csw = width, csh = height;
    #pragma unroll
    for (int d = 1; d < 32; d <<= 1) {
        float t  = __shfl_up_sync(FULL, csw, d);
        float t2 = __shfl_up_sync(FULL, csh, d);
        if (lane >= d) { csw += t; csh += t2; }
    }

    float cwL = __shfl_up_sync(FULL, csw, 1); if (lane == 0) cwL = 0.0f;
    float chL = __shfl_up_sync(FULL, csh, 1); if (lane == 0) chL = 0.0f;

    float slope  = height / width;
    float slopeN = __shfl_down_sync(FULL, slope, 1);
    float widthN = __shfl_down_sync(FULL, width, 1);

    float min1 = fminf(fabsf(slope), fabsf(slopeN));
    float min2 = 0.5f * (widthN * slope + width * slopeN) / (width + widthN);
    float ms   = fminf(min1, min2);
    float sg   = (float)((slope  > 0.0f) - (slope  < 0.0f));
    float sgN  = (float)((slopeN > 0.0f) - (slopeN < 0.0f));
    float dInnerR = ms * (sg + sgN);

    float s0  = __shfl_sync(FULL, slope, 0);
    float s31 = __shfl_sync(FULL, slope, 31);
    float dl = (1.0f / (1.0f + __expf(-__ldg(&udl[f])))) * 3.0f * s0;
    float dr = (1.0f / (1.0f + __expf(-__ldg(&udr[f])))) * 3.0f * s31;

    float derivR = (lane == 31) ? dr : dInnerR;
    float derivL = __shfl_up_sync(FULL, derivR, 1);
    if (lane == 0) derivL = dl;

    float a = (derivL + derivR - 2.0f * slope) / (width * width);
    float b = (3.0f * slope - 2.0f * derivL - derivR) / width;

    int idx = f * KK + lane;
    g_coef[idx] = make_float4(a, b, derivL, chL);
    g_cwl[idx]  = cwL;
}

// ---------------------------------------------------------------------------
// Per-element eval: ALL table accesses via conflict-free LDS (bank == cnt),
// ZERO shuffles. lane = row. e8/e16/e24 are broadcast-loaded per feature.
// ---------------------------------------------------------------------------
static __device__ __forceinline__ void eval_one(
    float x,
    const float*  __restrict__ sWLf,   // cwl[0..31] of this feature
    const float4* __restrict__ sCf,    // coef[0..31] of this feature
    float e16, float e8, float e24,
    float* __restrict__ sXslot, int& ie, float& mA)
{
    // levels 1-2 on broadcast registers (pure ALU)
    int cnt = (e16 <= x) ? 16 : 0;
    float e2 = cnt ? e24 : e8;
    if (e2 <= x) cnt += 8;
    // levels 3-5: dependent scalar LDS, conflict-free (bank == index)
    if (sWLf[cnt + 4] <= x) cnt += 4;
    if (sWLf[cnt + 2] <= x) cnt += 2;
    if (sWLf[cnt + 1] <= x) cnt += 1;

    float4 cf = sCf[cnt];              // LDS.128 gather
    float  wl = sWLf[cnt];             // conflict-free scalar LDS

    float s0  = x - wl;
    float out = fmaf(fmaf(fmaf(cf.x, s0, cf.y), s0, cf.z), s0, cf.w);
    *sXslot = __saturatef(out);

    float deriv = fmaf(fmaf(3.0f * cf.x, s0, 2.0f * cf.y), s0, cf.z);
    float ad = fabsf(deriv);
    int bits = __float_as_int(ad);
    if ((bits & 0x7F800000) == 0) {        // denorm/zero renorm
        ad *= 18446744073709551616.0f;     // 2^64
        bits = __float_as_int(ad);
        ie -= 64;
    }
    ie += bits >> 23;
    mA *= __int_as_float((bits & 0x007FFFFF) | 0x3F800000);
}

// ---------------------------------------------------------------------------
// Kernel 2: evaluation. grid = (FG, RG) = (32, 64), 256 thr = 8 warps.
// Warp w: features [w*4, +4) of the block's 32, rows = 2 strips of 32.
// Feature pairs interleaved for ILP. No shuffles anywhere in the hot path.
// ---------------------------------------------------------------------------
__global__ void __launch_bounds__(256) spline_kernel(
    const float* __restrict__ inputs, float* __restrict__ outputs,
    float* __restrict__ sums)
{
    __shared__ float  sX[FPB * XPITCH];        // [feature][row]
    __shared__ float  sWL[FPB * 32];           // cwl tables
    __shared__ float4 sC[FPB * 32];            // coef tables
    __shared__ float  sRed[NSTRIP * 8 * 32];   // per-strip per-warp partials
    __shared__ int    sLast;

    int tid  = threadIdx.x;
    int w    = tid >> 5;
    int lane = tid & 31;
    int fgBase  = blockIdx.x * FPB;
    int rowBase = blockIdx.y * RPB;

    // stage tables (linear, coalesced)
    #pragma unroll
    for (int i = tid; i < FPB * 32; i += 256) {
        sWL[i] = g_cwl[fgBase * KK + i];
        sC[i]  = g_coef[fgBase * KK + i];
    }
    // stage x tile transposed: coalesced float4 LDG, scattered STS
    {
        int c4 = (tid & 7) * 4;
        #pragma unroll
        for (int r = tid >> 3; r < RPB; r += 32) {
            float4 v = *(const float4*)&inputs[(size_t)(rowBase + r) * DD + fgBase + c4];
            sX[(c4 + 0) * XPITCH + r] = v.x;
            sX[(c4 + 1) * XPITCH + r] = v.y;
            sX[(c4 + 2) * XPITCH + r] = v.z;
            sX[(c4 + 3) * XPITCH + r] = v.w;
        }
    }
    __syncthreads();

    int   ie[NSTRIP];
    float mA[NSTRIP];
    #pragma unroll
    for (int st = 0; st < NSTRIP; ++st) { ie[st] = 0; mA[st] = 1.0f; }

    #pragma unroll
    for (int i = 0; i < FPW; i += 2) {
        int f0 = w * FPW + i;
        int f1 = f0 + 1;
        const float*  sW0 = &sWL[f0 * 32];
        const float*  sW1 = &sWL[f1 * 32];
        const float4* sC0 = &sC[f0 * 32];
        const float4* sC1 = &sC[f1 * 32];

        // broadcast search levels (uniform-address LDS -> broadcast)
        float e16a = sW0[16], e8a = sW0[8], e24a = sW0[24];
        float e16b = sW1[16], e8b = sW1[8], e24b = sW1[24];

        #pragma unroll
        for (int st = 0; st < NSTRIP; ++st) {
            float x0 = sX[f0 * XPITCH + st * 32 + lane];
            float x1 = sX[f1 * XPITCH + st * 32 + lane];
            eval_one(x0, sW0, sC0, e16a, e8a, e24a,
                     &sX[f0 * XPITCH + st * 32 + lane], ie[st], mA[st]);
            eval_one(x1, sW1, sC1, e16b, e8b, e24b,
                     &sX[f1 * XPITCH + st * 32 + lane], ie[st], mA[st]);
        }
    }

    // per-strip per-warp partial (lane = row): one log2 per 4 features
    #pragma unroll
    for (int st = 0; st < NSTRIP; ++st)
        sRed[st * 256 + w * 32 + lane] =
            (float)(ie[st] - 127 * FPW) + __log2f(mA[st]);
    __syncthreads();

    // coalesced writeback of outputs from smem tile
    {
        int c4 = (tid & 7) * 4;
        #pragma unroll
        for (int r = tid >> 3; r < RPB; r += 32) {
            float4 v;
            v.x = sX[(c4 + 0) * XPITCH + r];
            v.y = sX[(c4 + 1) * XPITCH + r];
            v.z = sX[(c4 + 2) * XPITCH + r];
            v.w = sX[(c4 + 3) * XPITCH + r];
            *(float4*)&outputs[(size_t)(rowBase + r) * DD + fgBase + c4] = v;
        }
    }

    // block-level row partials -> global
    if (tid < RPB) {
        int strip = tid >> 5, lr = tid & 31;
        float s = 0.0f;
        #pragma unroll
        for (int ww = 0; ww < 8; ++ww) s += sRed[strip * 256 + ww * 32 + lr];
        g_partial[(size_t)(rowBase + tid) * FG + blockIdx.x] = s;
    }
    __threadfence();
    __syncthreads();
    if (tid == 0) sLast = (atomicAdd(&g_cnt[blockIdx.y], 1) == FG - 1);
    __syncthreads();

    if (sLast) {
        if (tid < RPB) {
            int row = rowBase + tid;
            const float4* p = (const float4*)&g_partial[(size_t)row * FG];
            float s = 0.0f;
            #pragma unroll
            for (int q = 0; q < FG / 4; ++q) {
                float4 v = __ldcg(p + q);
                s += ((v.x + v.y) + (v.z + v.w));
            }
            sums[row] = s * 0.69314718055994531f;   // ln(2)
        }
        if (tid == 0) g_cnt[blockIdx.y] = 0;        // self-reset for graph replay
    }
}

extern "C" void kernel_launch(void* const* d_in, const int* in_sizes, int n_in,
                              void* d_out, int out_size)
{
    const float* inputs = (const float*)d_in[0];
    const float* uw     = (const float*)d_in[1];
    const float* uh     = (const float*)d_in[2];
    const float* udl    = (const float*)d_in[3];
    const float* udr    = (const float*)d_in[4];
    float* out = (float*)d_out;

    precompute_kernel<<<DD / 4, 128>>>(uw, uh, udl, udr);
    dim3 grid(FG, RG);
    spline_kernel<<<grid, 256>>>(inputs, out, out + (size_t)BB * DD);
}